// round 2
// baseline (speedup 1.0000x reference)
#include <cuda_runtime.h>
#include <math.h>

#define Bv 2
#define Sv 1024
#define Ev 1024
#define Hv 16
#define HDv 64
#define TKv 64

// Scratch (allocation-free rule: __device__ globals)
__device__ float g_q[(size_t)Bv * Sv * Ev];
__device__ float g_k[(size_t)Bv * Sv * Ev];
__device__ float g_v[(size_t)Bv * Sv * Ev];
__device__ float g_attn[(size_t)Bv * Sv * Ev];
__device__ float g_scores[(size_t)Bv * Hv * Sv * Sv];  // 128 MB

// ---------------------------------------------------------------------------
// Generic C = alpha * (A[M,K] @ B[N,K]^T) + bias, all row-major, K contiguous.
// Block tile 64x64, K-tile 16, 256 threads, 4x4 per thread.
// Batch z decomposed as (z/zDiv, z%zDiv) with separate strides for A and B;
// C uses linear batch stride cS.
// M,N implied by grid (must be multiples of 64); K multiple of 16.
// ---------------------------------------------------------------------------
__global__ void __launch_bounds__(256)
gemm_abt(const float* __restrict__ A, int lda,
         const float* __restrict__ B, int ldb,
         float* __restrict__ C, int ldc,
         const float* __restrict__ bias,
         int K, float alpha,
         int zDiv, long aS1, long aS2, long bS1, long bS2, long cS)
{
    const int z = blockIdx.z;
    A += (long)(z / zDiv) * aS1 + (long)(z % zDiv) * aS2;
    B += (long)(z / zDiv) * bS1 + (long)(z % zDiv) * bS2;
    C += (long)z * cS;

    __shared__ float As[16][64];
    __shared__ float Bs[16][64];

    const int tid = threadIdx.x;
    const int tx = tid % 16;
    const int ty = tid / 16;
    const int rowBase = blockIdx.y * 64;
    const int colBase = blockIdx.x * 64;

    // loader mapping: 256 threads -> 64 rows x 4 float4
    const int lRow = tid >> 2;          // 0..63
    const int lC4  = (tid & 3) * 4;     // 0,4,8,12

    float acc[4][4] = {};

    for (int k0 = 0; k0 < K; k0 += 16) {
        float4 a4 = *(const float4*)&A[(long)(rowBase + lRow) * lda + k0 + lC4];
        As[lC4 + 0][lRow] = a4.x;
        As[lC4 + 1][lRow] = a4.y;
        As[lC4 + 2][lRow] = a4.z;
        As[lC4 + 3][lRow] = a4.w;
        float4 b4 = *(const float4*)&B[(long)(colBase + lRow) * ldb + k0 + lC4];
        Bs[lC4 + 0][lRow] = b4.x;
        Bs[lC4 + 1][lRow] = b4.y;
        Bs[lC4 + 2][lRow] = b4.z;
        Bs[lC4 + 3][lRow] = b4.w;
        __syncthreads();

        #pragma unroll
        for (int k = 0; k < 16; k++) {
            float4 av = *(const float4*)&As[k][ty * 4];
            float4 bv = *(const float4*)&Bs[k][tx * 4];
            float a[4] = {av.x, av.y, av.z, av.w};
            float b[4] = {bv.x, bv.y, bv.z, bv.w};
            #pragma unroll
            for (int i = 0; i < 4; i++)
                #pragma unroll
                for (int j = 0; j < 4; j++)
                    acc[i][j] += a[i] * b[j];
        }
        __syncthreads();
    }

    #pragma unroll
    for (int i = 0; i < 4; i++) {
        const int row = rowBase + ty * 4 + i;
        #pragma unroll
        for (int j = 0; j < 4; j++) {
            const int col = colBase + tx * 4 + j;
            float v = acc[i][j] * alpha;
            if (bias) v += bias[col];
            C[(long)row * ldc + col] = v;
        }
    }
}

// ---------------------------------------------------------------------------
// Per-(b,h,q) top-64 selection + softmax + weighted V gather.
// scores: [B,H,S,S] fp32 (already scaled by 1/sqrt(hd))
// V:      [B*S, E] row-major (head h slice at col h*64)
// out:    [B*S, E] row-major
// ---------------------------------------------------------------------------
__global__ void __launch_bounds__(256)
attn_topk(const float* __restrict__ scores,
          const float* __restrict__ V,
          float* __restrict__ out)
{
    __shared__ float sc[Sv];
    __shared__ float wv[TKv];
    __shared__ int   widx[TKv];
    __shared__ unsigned long long warpBest[8];
    __shared__ float pacc[4][HDv];
    __shared__ float sinv;

    const int bid = blockIdx.x;
    const int q  = bid % Sv;
    const int bh = bid / Sv;
    const int h  = bh % Hv;
    const int b  = bh / Hv;
    const int tid = threadIdx.x;

    const float* srow = scores + ((long)bh * Sv + q) * Sv;
    ((float4*)sc)[tid] = ((const float4*)srow)[tid];
    __syncthreads();

    // 64 rounds of argmax (tie -> smallest index, matches top_k semantics)
    for (int it = 0; it < TKv; it++) {
        unsigned long long best = 0;
        #pragma unroll
        for (int e = 0; e < 4; e++) {
            const int j = tid * 4 + e;
            unsigned u = __float_as_uint(sc[j]);
            u = (u & 0x80000000u) ? ~u : (u | 0x80000000u);
            unsigned long long key =
                ((unsigned long long)u << 32) | (unsigned)(0xFFFFFFFFu - j);
            best = best > key ? best : key;
        }
        #pragma unroll
        for (int off = 16; off; off >>= 1) {
            unsigned long long o = __shfl_down_sync(0xFFFFFFFFu, best, off);
            best = best > o ? best : o;
        }
        if ((tid & 31) == 0) warpBest[tid >> 5] = best;
        __syncthreads();
        if (tid == 0) {
            unsigned long long m = warpBest[0];
            #pragma unroll
            for (int w = 1; w < 8; w++) m = m > warpBest[w] ? m : warpBest[w];
            const int idx = (int)(0xFFFFFFFFu - (unsigned)(m & 0xFFFFFFFFu));
            unsigned u = (unsigned)(m >> 32);
            u = (u & 0x80000000u) ? (u & 0x7FFFFFFFu) : ~u;
            widx[it] = idx;
            wv[it]   = __uint_as_float(u);
            sc[idx]  = -__int_as_float(0x7F800000);  // -inf
        }
        __syncthreads();
    }

    // softmax over the 64 selected scores (wv[0] is the global max)
    const float m = wv[0];
    __syncthreads();
    if (tid < TKv) wv[tid] = expf(wv[tid] - m);
    __syncthreads();
    if (tid == 0) {
        float s = 0.f;
        #pragma unroll
        for (int i = 0; i < TKv; i++) s += wv[i];
        sinv = 1.0f / s;
    }
    __syncthreads();
    if (tid < TKv) wv[tid] *= sinv;
    __syncthreads();

    // out[d] = sum_j wv[j] * V[b, widx[j], h, d]; 4-way split over key range
    const int d   = tid & 63;
    const int seg = tid >> 6;
    const float* vb = V + (long)b * Sv * Ev + h * HDv + d;
    float acc = 0.f;
    #pragma unroll
    for (int j = seg * 16; j < seg * 16 + 16; j++)
        acc += wv[j] * vb[(long)widx[j] * Ev];
    pacc[seg][d] = acc;
    __syncthreads();
    if (tid < HDv) {
        float r = pacc[0][tid] + pacc[1][tid] + pacc[2][tid] + pacc[3][tid];
        out[((long)(b * Sv + q)) * Ev + h * HDv + tid] = r;
    }
}

extern "C" void kernel_launch(void* const* d_in, const int* in_sizes, int n_in,
                              void* d_out, int out_size)
{
    const float* x  = (const float*)d_in[0];
    const float* Wq = (const float*)d_in[1];
    const float* bq = (const float*)d_in[2];
    const float* Wk = (const float*)d_in[3];
    const float* bk = (const float*)d_in[4];
    const float* Wv = (const float*)d_in[5];
    const float* bv = (const float*)d_in[6];
    const float* Wo = (const float*)d_in[7];
    const float* bo = (const float*)d_in[8];
    float* outp = (float*)d_out;

    float *q, *k, *v, *attn, *sc;
    cudaGetSymbolAddress((void**)&q,    g_q);
    cudaGetSymbolAddress((void**)&k,    g_k);
    cudaGetSymbolAddress((void**)&v,    g_v);
    cudaGetSymbolAddress((void**)&attn, g_attn);
    cudaGetSymbolAddress((void**)&sc,   g_scores);

    const dim3 thr(256);

    // QKV projections: [2048,1024] @ [1024,1024]^T + bias
    const dim3 gp(Ev / 64, (Bv * Sv) / 64, 1);
    gemm_abt<<<gp, thr>>>(x, Ev, Wq, Ev, q, Ev, bq, Ev, 1.0f, 1, 0, 0, 0, 0, 0);
    gemm_abt<<<gp, thr>>>(x, Ev, Wk, Ev, k, Ev, bk, Ev, 1.0f, 1, 0, 0, 0, 0, 0);
    gemm_abt<<<gp, thr>>>(x, Ev, Wv, Ev, v, Ev, bv, Ev, 1.0f, 1, 0, 0, 0, 0, 0);

    // scores = Q K^T / 8 per (b,h): 32 batches of [1024,64]x[64,1024]
    const dim3 gs(Sv / 64, Sv / 64, Bv * Hv);
    gemm_abt<<<gs, thr>>>(q, Ev, k, Ev, sc, Sv, nullptr, HDv, 0.125f,
                          Hv, (long)Sv * Ev, (long)HDv,
                              (long)Sv * Ev, (long)HDv,
                          (long)Sv * Sv);

    // top-64 + softmax + weighted gather
    attn_topk<<<Bv * Hv * Sv, thr>>>(sc, v, attn);

    // output projection
    gemm_abt<<<gp, thr>>>(attn, Ev, Wo, Ev, outp, Ev, bo, Ev, 1.0f, 1, 0, 0, 0, 0, 0);
}

// round 3
// speedup vs baseline: 2.6586x; 2.6586x over previous
#include <cuda_runtime.h>
#include <math.h>

#define Bv 2
#define Sv 1024
#define Ev 1024
#define Hv 16
#define HDv 64
#define TKv 64

// Scratch (allocation-free rule: __device__ globals)
__device__ float g_q[(size_t)Bv * Sv * Ev];
__device__ float g_k[(size_t)Bv * Sv * Ev];
__device__ float g_v[(size_t)Bv * Sv * Ev];
__device__ float g_attn[(size_t)Bv * Sv * Ev];
__device__ float g_scores[(size_t)Bv * Hv * Sv * Sv];  // 128 MB

// ---------------------------------------------------------------------------
// C = alpha * (A[M,K] @ B[N,K]^T) + bias. Row-major, K contiguous.
// Block tile 128x128, K-tile 16, 256 threads, 8x8 microtile (split 4+4 at +64
// for conflict-free float4 LDS phases).
// Batch z -> (z/zDiv, z%zDiv) strides for A/B; C linear stride cS.
// ---------------------------------------------------------------------------
__global__ void __launch_bounds__(256)
gemm_abt(const float* __restrict__ A, int lda,
         const float* __restrict__ B, int ldb,
         float* __restrict__ C, int ldc,
         const float* __restrict__ bias,
         int K, float alpha,
         int zDiv, long aS1, long aS2, long bS1, long bS2, long cS)
{
    const int z = blockIdx.z;
    A += (long)(z / zDiv) * aS1 + (long)(z % zDiv) * aS2;
    B += (long)(z / zDiv) * bS1 + (long)(z % zDiv) * bS2;
    C += (long)z * cS;

    __shared__ float As[16][128];
    __shared__ float Bs[16][128];

    const int tid = threadIdx.x;
    const int tx = tid % 16;
    const int ty = tid / 16;
    const int rowBase = blockIdx.y * 128;
    const int colBase = blockIdx.x * 128;

    // loader: 256 threads -> 128 rows x 2 half-k-tiles (2 float4 each matrix)
    const int lRow = tid >> 1;         // 0..127
    const int lK   = (tid & 1) * 8;    // 0 or 8

    const float* Ag = A + (long)(rowBase + lRow) * lda + lK;
    const float* Bg = B + (long)(colBase + lRow) * ldb + lK;

    float acc[8][8] = {};

    for (int k0 = 0; k0 < K; k0 += 16) {
        float4 a0 = *(const float4*)(Ag + k0);
        float4 a1 = *(const float4*)(Ag + k0 + 4);
        float4 b0 = *(const float4*)(Bg + k0);
        float4 b1 = *(const float4*)(Bg + k0 + 4);
        As[lK + 0][lRow] = a0.x; As[lK + 1][lRow] = a0.y;
        As[lK + 2][lRow] = a0.z; As[lK + 3][lRow] = a0.w;
        As[lK + 4][lRow] = a1.x; As[lK + 5][lRow] = a1.y;
        As[lK + 6][lRow] = a1.z; As[lK + 7][lRow] = a1.w;
        Bs[lK + 0][lRow] = b0.x; Bs[lK + 1][lRow] = b0.y;
        Bs[lK + 2][lRow] = b0.z; Bs[lK + 3][lRow] = b0.w;
        Bs[lK + 4][lRow] = b1.x; Bs[lK + 5][lRow] = b1.y;
        Bs[lK + 6][lRow] = b1.z; Bs[lK + 7][lRow] = b1.w;
        __syncthreads();

        #pragma unroll
        for (int k = 0; k < 16; k++) {
            float4 av0 = *(const float4*)&As[k][ty * 4];
            float4 av1 = *(const float4*)&As[k][64 + ty * 4];
            float4 bv0 = *(const float4*)&Bs[k][tx * 4];
            float4 bv1 = *(const float4*)&Bs[k][64 + tx * 4];
            float a[8] = {av0.x, av0.y, av0.z, av0.w, av1.x, av1.y, av1.z, av1.w};
            float b[8] = {bv0.x, bv0.y, bv0.z, bv0.w, bv1.x, bv1.y, bv1.z, bv1.w};
            #pragma unroll
            for (int i = 0; i < 8; i++)
                #pragma unroll
                for (int j = 0; j < 8; j++)
                    acc[i][j] += a[i] * b[j];
        }
        __syncthreads();
    }

    float4 bias0 = {0, 0, 0, 0}, bias1 = {0, 0, 0, 0};
    if (bias) {
        bias0 = *(const float4*)&bias[colBase + tx * 4];
        bias1 = *(const float4*)&bias[colBase + 64 + tx * 4];
    }
    #pragma unroll
    for (int i = 0; i < 8; i++) {
        const int row = rowBase + ((i < 4) ? (ty * 4 + i) : (64 + ty * 4 + i - 4));
        float4 o0, o1;
        o0.x = acc[i][0] * alpha + bias0.x;
        o0.y = acc[i][1] * alpha + bias0.y;
        o0.z = acc[i][2] * alpha + bias0.z;
        o0.w = acc[i][3] * alpha + bias0.w;
        o1.x = acc[i][4] * alpha + bias1.x;
        o1.y = acc[i][5] * alpha + bias1.y;
        o1.z = acc[i][6] * alpha + bias1.z;
        o1.w = acc[i][7] * alpha + bias1.w;
        *(float4*)&C[(long)row * ldc + colBase + tx * 4]      = o0;
        *(float4*)&C[(long)row * ldc + colBase + 64 + tx * 4] = o1;
    }
}

// ---------------------------------------------------------------------------
// Per-(b,h,q) exact top-64 via MSB-first 8-bit radix select, then softmax +
// weighted V gather. Tie-break: smallest index (matches jax.lax.top_k).
// ---------------------------------------------------------------------------
__device__ __forceinline__ unsigned enc_key(float f) {
    unsigned u = __float_as_uint(f);
    return (u & 0x80000000u) ? ~u : (u | 0x80000000u);
}
__device__ __forceinline__ float dec_key(unsigned u) {
    unsigned o = (u & 0x80000000u) ? (u & 0x7FFFFFFFu) : ~u;
    return __uint_as_float(o);
}

__global__ void __launch_bounds__(256)
attn_topk(const float* __restrict__ scores,
          const float* __restrict__ V,
          float* __restrict__ out)
{
    __shared__ unsigned keys[Sv];
    __shared__ int bins[256];
    __shared__ int s_dw[2];          // [digit, new want]
    __shared__ unsigned scanWarp[8];
    __shared__ float wv[TKv];
    __shared__ int   widx[TKv];
    __shared__ float pacc[4][HDv];
    __shared__ float s_m, s_sinv;

    const int tid = threadIdx.x;
    const int bid = blockIdx.x;           // = bh*S + q
    const int bh  = bid / Sv;
    const int h   = bh % Hv;
    const int b   = bh / Hv;

    // load row + monotone key transform
    const float4 f4 = ((const float4*)(scores + (long)bid * Sv))[tid];
    keys[tid * 4 + 0] = enc_key(f4.x);
    keys[tid * 4 + 1] = enc_key(f4.y);
    keys[tid * 4 + 2] = enc_key(f4.z);
    keys[tid * 4 + 3] = enc_key(f4.w);
    __syncthreads();

    // ---- radix select: find T = 64th largest key ----
    unsigned prefix = 0;
    int want = TKv;
    #pragma unroll
    for (int pass = 0; pass < 4; pass++) {
        const int shift = 24 - 8 * pass;
        bins[tid] = 0;
        __syncthreads();
        #pragma unroll
        for (int e = 0; e < 4; e++) {
            const unsigned u = keys[tid * 4 + e];
            if (pass == 0 || (u >> (shift + 8)) == prefix)
                atomicAdd(&bins[(u >> shift) & 255], 1);
        }
        __syncthreads();
        if (tid < 32) {
            const int base = 255 - (tid << 3);
            int c[8], s = 0;
            #pragma unroll
            for (int j = 0; j < 8; j++) { c[j] = bins[base - j]; s += c[j]; }
            int incl = s;
            #pragma unroll
            for (int off = 1; off < 32; off <<= 1) {
                int o = __shfl_up_sync(0xFFFFFFFFu, incl, off);
                if (tid >= off) incl += o;
            }
            const int before = incl - s;
            if (before < want && want <= incl) {
                int run = before;
                #pragma unroll
                for (int j = 0; j < 8; j++) {
                    run += c[j];
                    if (run >= want) {
                        s_dw[0] = base - j;
                        s_dw[1] = want - (run - c[j]);
                        break;
                    }
                }
            }
        }
        __syncthreads();
        prefix = (prefix << 8) | (unsigned)s_dw[0];
        want = s_dw[1];
        __syncthreads();
    }
    const unsigned T = prefix;
    const int totalGt = TKv - want;

    // ---- packed (gt,eq) block prefix scan for deterministic placement ----
    unsigned u4[4];
    unsigned tsum = 0;
    #pragma unroll
    for (int e = 0; e < 4; e++) {
        u4[e] = keys[tid * 4 + e];
        tsum += (u4[e] > T) ? 0x10000u : (u4[e] == T ? 1u : 0u);
    }
    unsigned incl = tsum;
    #pragma unroll
    for (int off = 1; off < 32; off <<= 1) {
        unsigned o = __shfl_up_sync(0xFFFFFFFFu, incl, off);
        if ((tid & 31) >= off) incl += o;
    }
    if ((tid & 31) == 31) scanWarp[tid >> 5] = incl;
    __syncthreads();
    if (tid == 0) {
        unsigned run = 0;
        #pragma unroll
        for (int w = 0; w < 8; w++) { unsigned t = scanWarp[w]; scanWarp[w] = run; run += t; }
    }
    __syncthreads();
    const unsigned exclBase = scanWarp[tid >> 5] + (incl - tsum);
    int gtRun = (int)(exclBase >> 16);
    int eqRun = (int)(exclBase & 0xFFFFu);
    #pragma unroll
    for (int e = 0; e < 4; e++) {
        if (u4[e] > T) {
            wv[gtRun] = dec_key(u4[e]);
            widx[gtRun] = tid * 4 + e;
            gtRun++;
        } else if (u4[e] == T) {
            if (eqRun < want) {
                wv[totalGt + eqRun] = dec_key(u4[e]);
                widx[totalGt + eqRun] = tid * 4 + e;
            }
            eqRun++;
        }
    }
    __syncthreads();

    // ---- softmax over the 64 selected ----
    if (tid < 32) {
        float m = fmaxf(wv[tid], wv[tid + 32]);
        #pragma unroll
        for (int off = 16; off; off >>= 1)
            m = fmaxf(m, __shfl_xor_sync(0xFFFFFFFFu, m, off));
        if (tid == 0) s_m = m;
    }
    __syncthreads();
    if (tid < TKv) wv[tid] = expf(wv[tid] - s_m);
    __syncthreads();
    if (tid < 32) {
        float s = wv[tid] + wv[tid + 32];
        #pragma unroll
        for (int off = 16; off; off >>= 1)
            s += __shfl_xor_sync(0xFFFFFFFFu, s, off);
        if (tid == 0) s_sinv = 1.0f / s;
    }
    __syncthreads();
    if (tid < TKv) wv[tid] *= s_sinv;
    __syncthreads();

    // ---- out[d] = sum_j wv[j] * V[b, widx[j], h, d]; 4-way key split ----
    const int d   = tid & 63;
    const int seg = tid >> 6;
    const float* vb = V + (long)b * Sv * Ev + h * HDv + d;
    float acc = 0.f;
    #pragma unroll
    for (int j = seg * 16; j < seg * 16 + 16; j++)
        acc += wv[j] * vb[(long)widx[j] * Ev];
    pacc[seg][d] = acc;
    __syncthreads();
    if (tid < HDv) {
        const float r = pacc[0][tid] + pacc[1][tid] + pacc[2][tid] + pacc[3][tid];
        out[(long)bid / (Hv * Sv) * 0 + ((long)(b * Sv + (bid % Sv))) * Ev + h * HDv + tid] = r;
    }
}

extern "C" void kernel_launch(void* const* d_in, const int* in_sizes, int n_in,
                              void* d_out, int out_size)
{
    const float* x  = (const float*)d_in[0];
    const float* Wq = (const float*)d_in[1];
    const float* bq = (const float*)d_in[2];
    const float* Wk = (const float*)d_in[3];
    const float* bk = (const float*)d_in[4];
    const float* Wv = (const float*)d_in[5];
    const float* bv = (const float*)d_in[6];
    const float* Wo = (const float*)d_in[7];
    const float* bo = (const float*)d_in[8];
    float* outp = (float*)d_out;

    float *q, *k, *v, *attn, *sc;
    cudaGetSymbolAddress((void**)&q,    g_q);
    cudaGetSymbolAddress((void**)&k,    g_k);
    cudaGetSymbolAddress((void**)&v,    g_v);
    cudaGetSymbolAddress((void**)&attn, g_attn);
    cudaGetSymbolAddress((void**)&sc,   g_scores);

    const dim3 thr(256);

    // QKV projections: [2048,1024] @ [1024,1024]^T + bias
    const dim3 gp(Ev / 128, (Bv * Sv) / 128, 1);
    gemm_abt<<<gp, thr>>>(x, Ev, Wq, Ev, q, Ev, bq, Ev, 1.0f, 1, 0, 0, 0, 0, 0);
    gemm_abt<<<gp, thr>>>(x, Ev, Wk, Ev, k, Ev, bk, Ev, 1.0f, 1, 0, 0, 0, 0, 0);
    gemm_abt<<<gp, thr>>>(x, Ev, Wv, Ev, v, Ev, bv, Ev, 1.0f, 1, 0, 0, 0, 0, 0);

    // scores = Q K^T / 8 per (b,h): 32 batches of [1024,64]x[64,1024]
    const dim3 gs(Sv / 128, Sv / 128, Bv * Hv);
    gemm_abt<<<gs, thr>>>(q, Ev, k, Ev, sc, Sv, nullptr, HDv, 0.125f,
                          Hv, (long)Sv * Ev, (long)HDv,
                              (long)Sv * Ev, (long)HDv,
                          (long)Sv * Sv);

    // top-64 + softmax + weighted gather
    attn_topk<<<Bv * Hv * Sv, thr>>>(sc, v, attn);

    // output projection
    gemm_abt<<<gp, thr>>>(attn, Ev, Wo, Ev, outp, Ev, bo, Ev, 1.0f, 1, 0, 0, 0, 0, 0);
}

// round 7
// speedup vs baseline: 3.4198x; 1.2863x over previous
#include <cuda_runtime.h>
#include <math.h>

#define Bv 2
#define Sv 1024
#define Ev 1024
#define Hv 16
#define HDv 64
#define TKv 64

// Scratch (allocation-free rule: __device__ globals)
__device__ float g_q[(size_t)Bv * Sv * Ev];
__device__ float g_k[(size_t)Bv * Sv * Ev];
__device__ float g_v[(size_t)Bv * Sv * Ev];
__device__ float g_attn[(size_t)Bv * Sv * Ev];
__device__ float g_scores[(size_t)Bv * Hv * Sv * Sv];  // 128 MB

// ---------------------------------------------------------------------------
// Pipelined GEMM core: C = alpha * (A[M,K] @ B[N,K]^T) + bias. Row-major,
// K contiguous. Block tile 128x128, K-tile 16, 256 threads, 8x8 microtile.
// Register-staged prefetch of tile t+1 overlaps compute of tile t;
// double-buffered smem; ONE __syncthreads per K-tile.
// ---------------------------------------------------------------------------
__device__ __forceinline__ void gemm_core(
    const float* __restrict__ A, int lda,
    const float* __restrict__ B, int ldb,
    float* __restrict__ C, int ldc,
    const float* __restrict__ bias,
    int K, float alpha)
{
    __shared__ float As[32][128];   // two 16-deep buffers
    __shared__ float Bs[32][128];

    const int tid = threadIdx.x;
    const int tx = tid & 15;
    const int ty = tid >> 4;
    const int rowBase = blockIdx.y * 128;
    const int colBase = blockIdx.x * 128;

    // loader: 256 threads -> 128 rows x 2 half-k-tiles (2 float4 each matrix)
    const int lRow = tid >> 1;         // 0..127
    const int lK   = (tid & 1) * 8;    // 0 or 8

    const float* Ag = A + (size_t)(rowBase + lRow) * lda + lK;
    const float* Bg = B + (size_t)(colBase + lRow) * ldb + lK;

    // stage tile 0
    float4 a0 = *(const float4*)(Ag);
    float4 a1 = *(const float4*)(Ag + 4);
    float4 b0 = *(const float4*)(Bg);
    float4 b1 = *(const float4*)(Bg + 4);

    float acc[8][8] = {};
    const int ntiles = K >> 4;

    int buf = 0;
    for (int t = 0; t < ntiles; t++) {
        // commit staged regs into current buffer
        As[buf + lK + 0][lRow] = a0.x; As[buf + lK + 1][lRow] = a0.y;
        As[buf + lK + 2][lRow] = a0.z; As[buf + lK + 3][lRow] = a0.w;
        As[buf + lK + 4][lRow] = a1.x; As[buf + lK + 5][lRow] = a1.y;
        As[buf + lK + 6][lRow] = a1.z; As[buf + lK + 7][lRow] = a1.w;
        Bs[buf + lK + 0][lRow] = b0.x; Bs[buf + lK + 1][lRow] = b0.y;
        Bs[buf + lK + 2][lRow] = b0.z; Bs[buf + lK + 3][lRow] = b0.w;
        Bs[buf + lK + 4][lRow] = b1.x; Bs[buf + lK + 5][lRow] = b1.y;
        Bs[buf + lK + 6][lRow] = b1.z; Bs[buf + lK + 7][lRow] = b1.w;
        __syncthreads();

        // issue prefetch of tile t+1 (latency hidden under compute below)
        if (t + 1 < ntiles) {
            const int off = (t + 1) * 16;
            a0 = *(const float4*)(Ag + off);
            a1 = *(const float4*)(Ag + off + 4);
            b0 = *(const float4*)(Bg + off);
            b1 = *(const float4*)(Bg + off + 4);
        }

        #pragma unroll
        for (int k = 0; k < 16; k++) {
            float4 av0 = *(const float4*)&As[buf + k][ty * 4];
            float4 av1 = *(const float4*)&As[buf + k][64 + ty * 4];
            float4 bv0 = *(const float4*)&Bs[buf + k][tx * 4];
            float4 bv1 = *(const float4*)&Bs[buf + k][64 + tx * 4];
            float a[8] = {av0.x, av0.y, av0.z, av0.w, av1.x, av1.y, av1.z, av1.w};
            float b[8] = {bv0.x, bv0.y, bv0.z, bv0.w, bv1.x, bv1.y, bv1.z, bv1.w};
            #pragma unroll
            for (int i = 0; i < 8; i++)
                #pragma unroll
                for (int j = 0; j < 8; j++)
                    acc[i][j] += a[i] * b[j];
        }
        buf ^= 16;
    }

    float4 bias0 = {0, 0, 0, 0}, bias1 = {0, 0, 0, 0};
    if (bias) {
        bias0 = *(const float4*)&bias[colBase + tx * 4];
        bias1 = *(const float4*)&bias[colBase + 64 + tx * 4];
    }
    #pragma unroll
    for (int i = 0; i < 8; i++) {
        const int row = rowBase + ((i < 4) ? (ty * 4 + i) : (64 + ty * 4 + i - 4));
        float4 o0, o1;
        o0.x = acc[i][0] * alpha + bias0.x;
        o0.y = acc[i][1] * alpha + bias0.y;
        o0.z = acc[i][2] * alpha + bias0.z;
        o0.w = acc[i][3] * alpha + bias0.w;
        o1.x = acc[i][4] * alpha + bias1.x;
        o1.y = acc[i][5] * alpha + bias1.y;
        o1.z = acc[i][6] * alpha + bias1.z;
        o1.w = acc[i][7] * alpha + bias1.w;
        *(float4*)&C[(size_t)row * ldc + colBase + tx * 4]      = o0;
        *(float4*)&C[(size_t)row * ldc + colBase + 64 + tx * 4] = o1;
    }
}

// Fused QKV projection: grid.z selects weight/bias/output triple.
__global__ void __launch_bounds__(256, 2)
gemm_qkv(const float* __restrict__ x,
         const float* __restrict__ Wq, const float* __restrict__ bq,
         const float* __restrict__ Wk, const float* __restrict__ bk,
         const float* __restrict__ Wv, const float* __restrict__ bv,
         float* __restrict__ q, float* __restrict__ k, float* __restrict__ v)
{
    const float* W; const float* bias; float* C;
    if (blockIdx.z == 0)      { W = Wq; bias = bq; C = q; }
    else if (blockIdx.z == 1) { W = Wk; bias = bk; C = k; }
    else                      { W = Wv; bias = bv; C = v; }
    gemm_core(x, Ev, W, Ev, C, Ev, bias, Ev, 1.0f);
}

// Generic batched variant (scores + output projection).
__global__ void __launch_bounds__(256, 2)
gemm_abt(const float* __restrict__ A, int lda,
         const float* __restrict__ B, int ldb,
         float* __restrict__ C, int ldc,
         const float* __restrict__ bias,
         int K, float alpha,
         int zDiv, long aS1, long aS2, long bS1, long bS2, long cS)
{
    const int z = blockIdx.z;
    A += (long)(z / zDiv) * aS1 + (long)(z % zDiv) * aS2;
    B += (long)(z / zDiv) * bS1 + (long)(z % zDiv) * bS2;
    C += (long)z * cS;
    gemm_core(A, lda, B, ldb, C, ldc, bias, K, alpha);
}

// ---------------------------------------------------------------------------
// Per-(b,h,q) exact top-64 via MSB-first 8-bit radix select, then softmax +
// weighted V gather. Tie-break: smallest index (matches jax.lax.top_k).
// ---------------------------------------------------------------------------
__device__ __forceinline__ unsigned enc_key(float f) {
    unsigned u = __float_as_uint(f);
    return (u & 0x80000000u) ? ~u : (u | 0x80000000u);
}
__device__ __forceinline__ float dec_key(unsigned u) {
    unsigned o = (u & 0x80000000u) ? (u & 0x7FFFFFFFu) : ~u;
    return __uint_as_float(o);
}

__global__ void __launch_bounds__(256)
attn_topk(const float* __restrict__ scores,
          const float* __restrict__ V,
          float* __restrict__ out)
{
    __shared__ unsigned keys[Sv];
    __shared__ int bins[256];
    __shared__ int s_dw[2];          // [digit, new want]
    __shared__ unsigned scanWarp[8];
    __shared__ float wv[TKv];
    __shared__ int   widx[TKv];
    __shared__ float pacc[4][HDv];
    __shared__ float s_m, s_sinv;

    const int tid = threadIdx.x;
    const int bid = blockIdx.x;           // = bh*S + q
    const int bh  = bid / Sv;
    const int q   = bid % Sv;
    const int h   = bh % Hv;
    const int b   = bh / Hv;

    // load row + monotone key transform
    const float4 f4 = ((const float4*)(scores + (long)bid * Sv))[tid];
    keys[tid * 4 + 0] = enc_key(f4.x);
    keys[tid * 4 + 1] = enc_key(f4.y);
    keys[tid * 4 + 2] = enc_key(f4.z);
    keys[tid * 4 + 3] = enc_key(f4.w);
    __syncthreads();

    // ---- radix select: find T = 64th largest key ----
    unsigned prefix = 0;
    int want = TKv;
    #pragma unroll
    for (int pass = 0; pass < 4; pass++) {
        const int shift = 24 - 8 * pass;
        bins[tid] = 0;
        __syncthreads();
        #pragma unroll
        for (int e = 0; e < 4; e++) {
            const unsigned u = keys[tid * 4 + e];
            if (pass == 0 || (u >> (shift + 8)) == prefix)
                atomicAdd(&bins[(u >> shift) & 255], 1);
        }
        __syncthreads();
        if (tid < 32) {
            const int base = 255 - (tid << 3);
            int c[8], s = 0;
            #pragma unroll
            for (int j = 0; j < 8; j++) { c[j] = bins[base - j]; s += c[j]; }
            int incl = s;
            #pragma unroll
            for (int off = 1; off < 32; off <<= 1) {
                int o = __shfl_up_sync(0xFFFFFFFFu, incl, off);
                if (tid >= off) incl += o;
            }
            const int before = incl - s;
            if (before < want && want <= incl) {
                int run = before;
                #pragma unroll
                for (int j = 0; j < 8; j++) {
                    run += c[j];
                    if (run >= want) {
                        s_dw[0] = base - j;
                        s_dw[1] = want - (run - c[j]);
                        break;
                    }
                }
            }
        }
        __syncthreads();
        prefix = (prefix << 8) | (unsigned)s_dw[0];
        want = s_dw[1];
        __syncthreads();
    }
    const unsigned T = prefix;
    const int totalGt = TKv - want;

    // ---- packed (gt,eq) block prefix scan for deterministic placement ----
    unsigned u4[4];
    unsigned tsum = 0;
    #pragma unroll
    for (int e = 0; e < 4; e++) {
        u4[e] = keys[tid * 4 + e];
        tsum += (u4[e] > T) ? 0x10000u : (u4[e] == T ? 1u : 0u);
    }
    unsigned incl = tsum;
    #pragma unroll
    for (int off = 1; off < 32; off <<= 1) {
        unsigned o = __shfl_up_sync(0xFFFFFFFFu, incl, off);
        if ((tid & 31) >= off) incl += o;
    }
    if ((tid & 31) == 31) scanWarp[tid >> 5] = incl;
    __syncthreads();
    if (tid == 0) {
        unsigned run = 0;
        #pragma unroll
        for (int w = 0; w < 8; w++) { unsigned t = scanWarp[w]; scanWarp[w] = run; run += t; }
    }
    __syncthreads();
    const unsigned exclBase = scanWarp[tid >> 5] + (incl - tsum);
    int gtRun = (int)(exclBase >> 16);
    int eqRun = (int)(exclBase & 0xFFFFu);
    #pragma unroll
    for (int e = 0; e < 4; e++) {
        if (u4[e] > T) {
            wv[gtRun] = dec_key(u4[e]);
            widx[gtRun] = tid * 4 + e;
            gtRun++;
        } else if (u4[e] == T) {
            if (eqRun < want) {
                wv[totalGt + eqRun] = dec_key(u4[e]);
                widx[totalGt + eqRun] = tid * 4 + e;
            }
            eqRun++;
        }
    }
    __syncthreads();

    // ---- softmax over the 64 selected ----
    if (tid < 32) {
        float m = fmaxf(wv[tid], wv[tid + 32]);
        #pragma unroll
        for (int off = 16; off; off >>= 1)
            m = fmaxf(m, __shfl_xor_sync(0xFFFFFFFFu, m, off));
        if (tid == 0) s_m = m;
    }
    __syncthreads();
    if (tid < TKv) wv[tid] = expf(wv[tid] - s_m);
    __syncthreads();
    if (tid < 32) {
        float s = wv[tid] + wv[tid + 32];
        #pragma unroll
        for (int off = 16; off; off >>= 1)
            s += __shfl_xor_sync(0xFFFFFFFFu, s, off);
        if (tid == 0) s_sinv = 1.0f / s;
    }
    __syncthreads();
    if (tid < TKv) wv[tid] *= s_sinv;
    __syncthreads();

    // ---- out[d] = sum_j wv[j] * V[b, widx[j], h, d]; 4-way key split ----
    const int d   = tid & 63;
    const int seg = tid >> 6;
    const float* vb = V + (long)b * Sv * Ev + h * HDv + d;
    float acc = 0.f;
    #pragma unroll
    for (int j = seg * 16; j < seg * 16 + 16; j++)
        acc += wv[j] * vb[(long)widx[j] * Ev];
    pacc[seg][d] = acc;
    __syncthreads();
    if (tid < HDv) {
        const float r = pacc[0][tid] + pacc[1][tid] + pacc[2][tid] + pacc[3][tid];
        out[((long)(b * Sv + q)) * Ev + h * HDv + tid] = r;
    }
}

extern "C" void kernel_launch(void* const* d_in, const int* in_sizes, int n_in,
                              void* d_out, int out_size)
{
    const float* x  = (const float*)d_in[0];
    const float* Wq = (const float*)d_in[1];
    const float* bq = (const float*)d_in[2];
    const float* Wk = (const float*)d_in[3];
    const float* bk = (const float*)d_in[4];
    const float* Wv = (const float*)d_in[5];
    const float* bv = (const float*)d_in[6];
    const float* Wo = (const float*)d_in[7];
    const float* bo = (const float*)d_in[8];
    float* outp = (float*)d_out;

    float *q, *k, *v, *attn, *sc;
    cudaGetSymbolAddress((void**)&q,    g_q);
    cudaGetSymbolAddress((void**)&k,    g_k);
    cudaGetSymbolAddress((void**)&v,    g_v);
    cudaGetSymbolAddress((void**)&attn, g_attn);
    cudaGetSymbolAddress((void**)&sc,   g_scores);

    const dim3 thr(256);

    // Fused QKV projections: [2048,1024] @ [1024,1024]^T + bias, z selects W
    const dim3 gqkv(Ev / 128, (Bv * Sv) / 128, 3);
    gemm_qkv<<<gqkv, thr>>>(x, Wq, bq, Wk, bk, Wv, bv, q, k, v);

    // scores = Q K^T / 8 per (b,h): 32 batches of [1024,64]x[64,1024]
    const dim3 gs(Sv / 128, Sv / 128, Bv * Hv);
    gemm_abt<<<gs, thr>>>(q, Ev, k, Ev, sc, Sv, nullptr, HDv, 0.125f,
                          Hv, (long)Sv * Ev, (long)HDv,
                              (long)Sv * Ev, (long)HDv,
                          (long)Sv * Sv);

    // top-64 + softmax + weighted gather
    attn_topk<<<Bv * Hv * Sv, thr>>>(sc, v, attn);

    // output projection
    const dim3 gp(Ev / 128, (Bv * Sv) / 128, 1);
    gemm_abt<<<gp, thr>>>(attn, Ev, Wo, Ev, outp, Ev, bo, Ev, 1.0f,
                          1, 0, 0, 0, 0, 0);
}